// round 15
// baseline (speedup 1.0000x reference)
#include <cuda_runtime.h>
#include <cuda_fp16.h>

// Problem constants (fixed by the dataset)
#define NB 8
#define NC 128
#define EO 48000
#define NU 8000
#define EN 72000            // EO + 3*NU
#define U2 16000            // 2*NU
#define NUNIT 32000         // EO - 2*NU (survivors)

// smem table per CTA: 48000 f16 feature entries + 8000 f16 precomputed
// "new" combined entries = 56000 * 2 B = 112000 B -> 2 CTAs per SM.
#define TBL (EO + NU)
#define SMEM_BYTES (TBL * 2)

// 4-byte meta per output j (shared by all channels of batch b):
//   bits [0:16)  src (u16, < 56000)   bits [16:32) w (f16)
//   out[chan, j] = w * F[src]
// survivors: src=e, w=1. left/new_left: src=u, w=lw0/lw1.
// right/new_right: src=NU+u, w=rw0/rw1. new: src=EO+u, w=1 (value
// precomputed in-kernel as 0.5*(lw2*lf + rw2*rf)).
__device__ __align__(16) unsigned g_meta4[NB * EN];
// Halved third weights for the in-kernel "new" precompute.
__device__ __align__(16) float g_w2l[NB * NU];
__device__ __align__(16) float g_w2r[NB * NU];

__device__ __forceinline__ unsigned short h16(float x) {
    return __half_as_ushort(__float2half_rn(x));
}

// Fused meta build. All five destination sets are disjoint slices of one
// permutation -> every j written exactly once, no ordering needed.
__global__ void k_build(const int* __restrict__ old_idx,
                        const float* __restrict__ weights,
                        const int* __restrict__ left_idx,
                        const int* __restrict__ right_idx,
                        const int* __restrict__ new_idx,
                        const int* __restrict__ new_left_idx,
                        const int* __restrict__ new_right_idx) {
    const int NBASE = NB * NUNIT / 4;   // 64000 : survivors, int4
    const int NEDGE = NB * NU / 4;      // 16000 : edges, int4 x5
    int t = blockIdx.x * blockDim.x + threadIdx.x;
    const unsigned ONE = 0x3C00u << 16;               // f16 1.0 in w slot
    if (t < NBASE) {
        int b = t / (NUNIT / 4);
        int r = t - b * (NUNIT / 4);
        int4 o = ((const int4*)old_idx)[b * (EO / 4) + (U2 / 4) + r];
        int e0 = U2 + 4 * r;                          // src = full row index
        int base = b * EN;
        g_meta4[base + o.x] = (unsigned)(e0 + 0) | ONE;
        g_meta4[base + o.y] = (unsigned)(e0 + 1) | ONE;
        g_meta4[base + o.z] = (unsigned)(e0 + 2) | ONE;
        g_meta4[base + o.w] = (unsigned)(e0 + 3) | ONE;
    } else if (t < NBASE + NEDGE) {
        int t2 = t - NBASE;
        int b = t2 / (NU / 4);
        int r = t2 - b * (NU / 4);
        int u0 = 4 * r;
        int base = b * EN;
        int goff = b * (NU / 4) + r;
        int4 li  = ((const int4*)left_idx)[goff];
        int4 ri  = ((const int4*)right_idx)[goff];
        int4 ni  = ((const int4*)new_idx)[goff];
        int4 nli = ((const int4*)new_left_idx)[goff];
        int4 nri = ((const int4*)new_right_idx)[goff];
        int jl[4]  = {li.x,  li.y,  li.z,  li.w};
        int jr[4]  = {ri.x,  ri.y,  ri.z,  ri.w};
        int jn[4]  = {ni.x,  ni.y,  ni.z,  ni.w};
        int jnl[4] = {nli.x, nli.y, nli.z, nli.w};
        int jnr[4] = {nri.x, nri.y, nri.z, nri.w};
        const float* wbase = weights + ((size_t)b * NU + u0) * 6;
        #pragma unroll
        for (int k = 0; k < 4; k++) {
            int u = u0 + k;
            const float* w = wbase + k * 6;
            g_meta4[base + jl[k]]  = (unsigned)u
                                   | ((unsigned)h16(w[0]) << 16);
            g_meta4[base + jnl[k]] = (unsigned)u
                                   | ((unsigned)h16(w[1]) << 16);
            g_meta4[base + jr[k]]  = (unsigned)(u + NU)
                                   | ((unsigned)h16(w[3]) << 16);
            g_meta4[base + jnr[k]] = (unsigned)(u + NU)
                                   | ((unsigned)h16(w[4]) << 16);
            g_meta4[base + jn[k]]  = (unsigned)(EO + u) | ONE;
            g_w2l[b * NU + u] = 0.5f * w[2];
            g_w2r[b * NU + u] = 0.5f * w[5];
        }
    }
}

// Per-entry gather step: one random LDS.16, one cvt, one FMUL.
__device__ __forceinline__ float proc(unsigned m, unsigned fbase) {
    unsigned short fb;
    asm volatile("ld.shared.u16 %0, [%1];"
                 : "=h"(fb) : "r"(fbase + 2u * (m & 0xFFFFu)));
    float f = __half2float(__ushort_as_half(fb));
    float w = __half2float(__ushort_as_half((unsigned short)(m >> 16)));
    return w * f;
}

// Main kernel: one CTA per (b, c), 2 CTAs per SM (112 KB table each) so
// co-resident CTAs overlap fill (DRAM reads) with gather (DRAM writes).
// Fill: row -> f16 table + precomputed "new" entries. Gather: 4B meta
// (1 LDG.128 per 4 outputs), 1 LDS.16 per output, streaming float4 stores,
// pair-processing + rolling prefetch.
__global__ __launch_bounds__(1024, 2)
void k_main(const float* __restrict__ features, float* __restrict__ out) {
    extern __shared__ __half F[];       // [TBL]
    const int b = blockIdx.y;
    const int c = blockIdx.x;
    const int tid = threadIdx.x;

    const float* row = features + (size_t)(b * NC + c) * EO;

    // Stage 1: pack the feature row to f16 (float4 reads, uint2 writes).
    {
        const float4* r4 = (const float4*)row;
        uint2* f2 = (uint2*)F;
        #pragma unroll 4
        for (int i = tid; i < EO / 4; i += 1024) {
            float4 a = __ldcs(r4 + i);
            __half2 h0 = __floats2half2_rn(a.x, a.y);
            __half2 h1 = __floats2half2_rn(a.z, a.w);
            uint2 pk;
            pk.x = *reinterpret_cast<unsigned*>(&h0);
            pk.y = *reinterpret_cast<unsigned*>(&h1);
            f2[i] = pk;
        }
    }
    __syncthreads();

    // Stage 2: precompute the "new" combined entries F[EO+u].
    {
        const float* wl = g_w2l + b * NU;
        const float* wr = g_w2r + b * NU;
        #pragma unroll 2
        for (int u = tid; u < NU; u += 1024) {
            float lf = __half2float(F[u]);
            float rf = __half2float(F[u + NU]);
            float a = __ldg(wl + u);
            float r = __ldg(wr + u);
            F[EO + u] = __float2half_rn(fmaf(a, lf, r * rf));
        }
    }
    __syncthreads();

    unsigned fbase = (unsigned)__cvta_generic_to_shared(F);
    const int4* mm = (const int4*)(g_meta4 + b * EN);
    float4* o4 = (float4*)(out + (size_t)(b * NC + c) * EN);
    const int NT = EN / 4;              // 18000 quads

    // Pair-processing with rolling prefetch (two int4 metas in flight).
    int t = tid;
    int4 m0 = __ldg(mm + t);            // t < 1024 < NT
    int4 m1 = __ldg(mm + t + 1024);     // t+1024 < 2048 < NT

    while (true) {
        int ta = t + 2048;
        int tb = ta + 1024;
        bool ha = ta < NT;
        bool hb = tb < NT;
        int4 p0 = ha ? __ldg(mm + ta) : m0;
        int4 p1 = hb ? __ldg(mm + tb) : m1;

        float4 v;
        v.x = proc((unsigned)m0.x, fbase);
        v.y = proc((unsigned)m0.y, fbase);
        v.z = proc((unsigned)m0.z, fbase);
        v.w = proc((unsigned)m0.w, fbase);
        __stcs(o4 + t, v);

        if (t + 1024 < NT) {
            float4 u;
            u.x = proc((unsigned)m1.x, fbase);
            u.y = proc((unsigned)m1.y, fbase);
            u.z = proc((unsigned)m1.z, fbase);
            u.w = proc((unsigned)m1.w, fbase);
            __stcs(o4 + t + 1024, u);
        }

        if (!ha) break;
        m0 = p0; m1 = p1; t = ta;
    }
}

extern "C" void kernel_launch(void* const* d_in, const int* in_sizes, int n_in,
                              void* d_out, int out_size) {
    const float* features      = (const float*)d_in[0];
    const float* weights       = (const float*)d_in[1];
    const int*   old_idx       = (const int*)d_in[2];
    const int*   left_idx      = (const int*)d_in[3];
    const int*   right_idx     = (const int*)d_in[4];
    const int*   new_idx       = (const int*)d_in[5];
    const int*   new_left_idx  = (const int*)d_in[6];
    const int*   new_right_idx = (const int*)d_in[7];
    float* out = (float*)d_out;

    cudaFuncSetAttribute(k_main, cudaFuncAttributeMaxDynamicSharedMemorySize,
                         SMEM_BYTES);

    const int nbuild = NB * NUNIT / 4 + NB * NU / 4;   // 80000 threads
    k_build<<<(nbuild + 255) / 256, 256>>>(old_idx, weights, left_idx,
                                           right_idx, new_idx,
                                           new_left_idx, new_right_idx);
    dim3 grid(NC, NB);
    k_main<<<grid, 1024, SMEM_BYTES>>>(features, out);
}